// round 13
// baseline (speedup 1.0000x reference)
#include <cuda_runtime.h>
#include <cuda_bf16.h>
#include <math.h>

#define NTHREADS 256
#define HLEN     200
#define DIM      64
#define MAXB     4096

// ---- K1 dynamic smem layout ----
// bf16 tiles: 128B rows, chunk-XOR swizzle: byte(row,chunk)=row*128+((chunk^(row&7))<<4)
#define AHI_OFF   0                      // hist hi: 208 x 64 bf16 = 26624 B
#define BHI_OFF   26624                  // M hi: 64(k-rows) x 64 bf16 = 8192 B
#define F_TGT   8704                     // float index; 64
#define F_C     (F_TGT + 64)             // 64
#define F_W2    (F_C + 64)               // 64
#define F_SC    (F_W2 + 64)              // 200
#define F_RED   (F_SC + 200)             // 512
#define F_HID   (F_RED + 512)            // 200 (int)
#define F_SPAD  (F_HID + 200)            // 1
#define SMEM_FLOATS (F_SPAD + 4)
#define SMEM_BYTES  (SMEM_FLOATS * 4)    // ~39.3 KB -> 4 CTAs/SM

// inter-kernel scratch: comb = [tgt, pooled, pooled - tgt] per batch row
__device__ float g_comb[MAXB * 192];

__device__ __forceinline__ unsigned smem_u32(const void* p) {
    unsigned a;
    asm("{ .reg .u64 t; cvta.to.shared.u64 t, %1; cvt.u32.u64 %0, t; }"
        : "=r"(a) : "l"(p));
    return a;
}

#define LDSM_X4(r0, r1, r2, r3, addr) \
    asm volatile("ldmatrix.sync.aligned.m8n8.x4.shared.b16 {%0,%1,%2,%3}, [%4];" \
        : "=r"(r0), "=r"(r1), "=r"(r2), "=r"(r3) : "r"(addr))

#define LDSM_X2T(r0, r1, addr) \
    asm volatile("ldmatrix.sync.aligned.m8n8.x2.trans.shared.b16 {%0,%1}, [%2];" \
        : "=r"(r0), "=r"(r1) : "r"(addr))

#define MMA_BF16(d0, d1, d2, d3, a0, a1, a2, a3, b0, b1) \
    asm volatile("mma.sync.aligned.m16n8k16.row.col.f32.bf16.bf16.f32 " \
        "{%0,%1,%2,%3}, {%4,%5,%6,%7}, {%8,%9}, {%0,%1,%2,%3};" \
        : "+f"(d0), "+f"(d1), "+f"(d2), "+f"(d3) \
        : "r"(a0), "r"(a1), "r"(a2), "r"(a3), "r"(b0), "r"(b1))

__global__ __launch_bounds__(NTHREADS, 4)
void din_kernel(const int*   __restrict__ item_ids,
                const int*   __restrict__ history,
                const int*   __restrict__ hist_len,
                const float* __restrict__ emb,
                const float* __restrict__ aW1,
                const float* __restrict__ ab1,
                const float* __restrict__ aW2)
{
    extern __shared__ float sm[];
    char*  smc    = (char*)sm;
    float* tgt_s  = sm + F_TGT;
    float* c_s    = sm + F_C;
    float* w2_s   = sm + F_W2;
    float* sc_s   = sm + F_SC;
    float* red_s  = sm + F_RED;
    int*   hid_s  = (int*)(sm + F_HID);
    float* spad_s = sm + F_SPAD;

    const int b    = blockIdx.x;
    const int tid  = threadIdx.x;
    const int lane = tid & 31;
    const int wid  = tid >> 5;
    const unsigned sbase = smem_u32(sm);

    // ---- S0: history ids + target embedding + w2
    if (tid < HLEN) hid_s[tid] = history[b * HLEN + tid];
    if (tid < 16) {
        int iid = item_ids[b];
        ((float4*)tgt_s)[tid] = ((const float4*)(emb + (size_t)iid * DIM))[tid];
    }
    if (tid < DIM) w2_s[tid] = __ldg(aW2 + tid);
    __syncthreads();                                    // sync A

    const int hlen = hist_len[b];
    const int nt   = min(13, (hlen + 15) >> 4);   // live m16-tiles
    const int gtot = nt * 256;                    // rows*16 float4 chunks

    // ---- S1a: coalesced gather -> single bf16 hi tile (live rows only).
    for (int base = 0; base < gtot; base += 4 * NTHREADS) {
        float4 v[4];
        #pragma unroll
        for (int u = 0; u < 4; u++) {
            int idx = base + u * NTHREADS + tid;
            if (idx < gtot) {
                int row = idx >> 4;
                int c   = idx & 15;
                v[u] = make_float4(0.f, 0.f, 0.f, 0.f);
                if (row < hlen)
                    v[u] = ((const float4*)(emb + (size_t)hid_s[row] * DIM))[c];
            }
        }
        #pragma unroll
        for (int u = 0; u < 4; u++) {
            int idx = base + u * NTHREADS + tid;
            if (idx < gtot) {
                int row = idx >> 4;
                int c   = idx & 15;
                __nv_bfloat162 h01 = __floats2bfloat162_rn(v[u].x, v[u].y);
                __nv_bfloat162 h23 = __floats2bfloat162_rn(v[u].z, v[u].w);
                int byteoff = row * 128 + (((c >> 1) ^ (row & 7)) << 4) + (c & 1) * 8;
                *(uint2*)(smc + AHI_OFF + byteoff) =
                    make_uint2(*(unsigned*)&h01, *(unsigned*)&h23);
            }
        }
    }

    // ---- S1b: B tile (M[d][j] = A1[d][j] + tgt[d]*A3[d][j]) bf16, coalesced,
    //           fused with c_j partials (sum_d tgt[d]*A2[d][j]).
    {
        const int jp = tid & 31;
        const int g8 = tid >> 5;
        const int j0 = jp * 2;
        float p0 = 0.f, p1 = 0.f;
        #pragma unroll
        for (int d = g8 * 8; d < g8 * 8 + 8; d++) {
            float t = tgt_s[d];
            float2 a1 = __ldg((const float2*)(aW1 + d * DIM + j0));
            float2 a2 = __ldg((const float2*)(aW1 + (64 + d) * DIM + j0));
            float2 a3 = __ldg((const float2*)(aW1 + (128 + d) * DIM + j0));
            float m0 = fmaf(t, a3.x, a1.x);
            float m1 = fmaf(t, a3.y, a1.y);
            p0 = fmaf(t, a2.x, p0);
            p1 = fmaf(t, a2.y, p1);
            __nv_bfloat162 h = __floats2bfloat162_rn(m0, m1);
            int byteoff = d * 128 + ((((unsigned)j0 >> 3) ^ (d & 7)) << 4) + (j0 & 7) * 2;
            *(unsigned*)(smc + BHI_OFF + byteoff) = *(unsigned*)&h;
        }
        red_s[g8 * 64 + j0]     = p0;
        red_s[g8 * 64 + j0 + 1] = p1;
    }
    __syncthreads();                                    // sync B

    // ---- S2: finalize c_j; stage relu(c)*w2 for s_pad in red_s[256..319]
    if (tid < DIM) {
        float c = __ldg(ab1 + tid);
        #pragma unroll
        for (int g = 0; g < 8; g++) c += red_s[g * 64 + tid];
        c_s[tid]         = c;
        red_s[256 + tid] = fmaxf(c, 0.f) * w2_s[tid];
    }
    __syncthreads();                                    // sync C

    // ---- S3a: warp 0 reduces s_pad
    if (wid == 0) {
        float v = red_s[256 + lane] + red_s[288 + lane];
        #pragma unroll
        for (int o = 16; o; o >>= 1) v += __shfl_xor_sync(0xffffffffu, v, o);
        if (lane == 0) spad_s[0] = v;
    }

    // ---- S3b: scores GEMM on tensor pipe (single bf16 term).
    {
        const int m_off = ((lane >> 3) & 1) * 8 + (lane & 7);
        const int khalf = lane >> 4;
        const int bko   = ((lane >> 3) & 1) * 8 + (lane & 7);

        for (int mt = wid; mt < nt; mt += 8) {
            unsigned aH[4][4];
            const int r = mt * 16 + m_off;
            #pragma unroll
            for (int k = 0; k < 4; k++) {
                unsigned ad = sbase + AHI_OFF + r * 128 + ((((k << 1) + khalf) ^ (r & 7)) << 4);
                LDSM_X4(aH[k][0], aH[k][1], aH[k][2], aH[k][3], ad);
            }

            float s0 = 0.f, s1 = 0.f;
            #pragma unroll
            for (int n = 0; n < 8; n++) {
                float d0 = 0.f, d1 = 0.f, d2 = 0.f, d3 = 0.f;
                #pragma unroll
                for (int k = 0; k < 4; k++) {
                    int drow = k * 16 + bko;
                    unsigned bd = sbase + BHI_OFF + drow * 128 + ((n ^ (drow & 7)) << 4);
                    unsigned bh0, bh1;
                    LDSM_X2T(bh0, bh1, bd);
                    MMA_BF16(d0, d1, d2, d3, aH[k][0], aH[k][1], aH[k][2], aH[k][3], bh0, bh1);
                }
                int j0 = n * 8 + 2 * (lane & 3);
                float c0 = c_s[j0], c1 = c_s[j0 + 1];
                float w0 = w2_s[j0], w1 = w2_s[j0 + 1];
                s0 = fmaf(fmaxf(d0 + c0, 0.f), w0, s0);
                s0 = fmaf(fmaxf(d1 + c1, 0.f), w1, s0);
                s1 = fmaf(fmaxf(d2 + c0, 0.f), w0, s1);
                s1 = fmaf(fmaxf(d3 + c1, 0.f), w1, s1);
            }
            s0 += __shfl_xor_sync(0xffffffffu, s0, 1);
            s0 += __shfl_xor_sync(0xffffffffu, s0, 2);
            s1 += __shfl_xor_sync(0xffffffffu, s1, 1);
            s1 += __shfl_xor_sync(0xffffffffu, s1, 2);
            if ((lane & 3) == 0) {
                int l = mt * 16 + (lane >> 2);
                if (l < HLEN)     sc_s[l]     = s0;
                if (l + 8 < HLEN) sc_s[l + 8] = s1;
            }
        }
    }
    __syncthreads();                                    // sync D

    // ---- S4: fill rows beyond live tiles with s_pad
    {
        float sp = spad_s[0];
        int filled = nt * 16;
        for (int l = filled + tid; l < HLEN; l += NTHREADS) sc_s[l] = sp;
    }
    __syncthreads();                                    // sync E

    // ---- S5: softmax over sc_s[0..199]
    {
        float v = (tid < HLEN) ? sc_s[tid] : -INFINITY;
        float m = v;
        #pragma unroll
        for (int o = 16; o; o >>= 1) m = fmaxf(m, __shfl_xor_sync(0xffffffffu, m, o));
        if (lane == 0) red_s[wid] = m;
        __syncthreads();
        float mm = red_s[0];
        #pragma unroll
        for (int w = 1; w < 8; w++) mm = fmaxf(mm, red_s[w]);

        float e = (tid < HLEN) ? __expf(v - mm) : 0.f;
        float ssum = e;
        #pragma unroll
        for (int o = 16; o; o >>= 1) ssum += __shfl_xor_sync(0xffffffffu, ssum, o);
        if (lane == 0) red_s[8 + wid] = ssum;
        __syncthreads();
        float tot = red_s[8];
        #pragma unroll
        for (int w = 1; w < 8; w++) tot += red_s[8 + w];
        float inv = 1.f / tot;
        if (tid < HLEN) sc_s[tid] = e * inv;
    }
    __syncthreads();

    // ---- S6: pooled[d] = sum_{l<hlen} w[l]*emb[hid[l]][d] — exact fp32 from L2.
    {
        float p0 = 0.f, p1 = 0.f;
        const int dp = lane;
        for (int l = wid; l < hlen; l += 8) {
            float w = sc_s[l];
            float2 hv = __ldg((const float2*)(emb + (size_t)hid_s[l] * DIM) + dp);
            p0 = fmaf(w, hv.x, p0);
            p1 = fmaf(w, hv.y, p1);
        }
        red_s[wid * 64 + 2 * dp]     = p0;
        red_s[wid * 64 + 2 * dp + 1] = p1;
    }
    __syncthreads();

    // ---- S7: write comb = [tgt, pooled, pooled - tgt] to global scratch
    if (tid < DIM) {
        float pooled = 0.f;
        #pragma unroll
        for (int w = 0; w < 8; w++) pooled += red_s[w * 64 + tid];
        float tg = tgt_s[tid];
        float* gc = g_comb + (size_t)b * 192;
        gc[tid]        = tg;
        gc[64 + tid]   = pooled;
        gc[128 + tid]  = pooled - tg;
    }
}

// ============================ kernel 2: batched MLP ==========================
// 1024 threads/CTA, 1 CTA/SM (smem-capped). 28 rows/CTA -> grid 147.
// Weights staged once in smem; 32 warps hide LDS/staging latency.
#define K2_THREADS 1024
#define K2_ROWS 28

#define S2_W1   0                        // 192x128 = 24576
#define S2_W2   24576                    // 128x64  = 8192
#define S2_W3   32768                    // 64
#define S2_B1   32832                    // 128
#define S2_B2   32960                    // 64
#define S2_CMB  33024                    // 32x192  = 6144 (rows padded to 32)
#define S2_Z1   39168                    // 32x128  = 4096
#define S2_Z2   43264                    // 32x64   = 2048
#define K2_SMEM_FLOATS 45312
#define K2_SMEM_BYTES  (K2_SMEM_FLOATS * 4)

__global__ __launch_bounds__(K2_THREADS, 1)
void mlp_kernel(const float* __restrict__ fW1, const float* __restrict__ fb1,
                const float* __restrict__ fW2, const float* __restrict__ fb2,
                const float* __restrict__ fW3, const float* __restrict__ fb3,
                float* __restrict__ out, int nb)
{
    extern __shared__ float s2[];
    float* W1s = s2 + S2_W1;
    float* W2s = s2 + S2_W2;
    float* W3s = s2 + S2_W3;
    float* B1s = s2 + S2_B1;
    float* B2s = s2 + S2_B2;
    float* Cs  = s2 + S2_CMB;
    float* Z1s = s2 + S2_Z1;
    float* Z2s = s2 + S2_Z2;

    const int tid = threadIdx.x;
    const int r0  = blockIdx.x * K2_ROWS;

    // ---- stage weights + biases + comb (1024-way parallel, float4)
    for (int i = tid; i < 6144; i += K2_THREADS)
        ((float4*)W1s)[i] = __ldg((const float4*)fW1 + i);
    for (int i = tid; i < 2048; i += K2_THREADS)
        ((float4*)W2s)[i] = __ldg((const float4*)fW2 + i);
    if (tid < 64)  W3s[tid] = __ldg(fW3 + tid);
    if (tid < 128) B1s[tid] = __ldg(fb1 + tid);
    if (tid >= 128 && tid < 192) B2s[tid - 128] = __ldg(fb2 + tid - 128);
    for (int i = tid; i < 32 * 48; i += K2_THREADS) {
        int row = i / 48;
        int cc  = i - row * 48;
        float4 v = make_float4(0.f, 0.f, 0.f, 0.f);
        if (row < K2_ROWS && r0 + row < nb)
            v = ((const float4*)g_comb)[(size_t)(r0 + row) * 48 + cc];
        ((float4*)Cs)[i] = v;
    }
    __syncthreads();

    // ---- layer 1: thread = (j: 1 col of 128, rg: 4 rows of 32)
    {
        const int j  = tid & 127;
        const int rg = tid >> 7;      // 0..7 -> rows 4rg..4rg+3
        float bias = B1s[j];
        float a0 = bias, a1 = bias, a2 = bias, a3 = bias;

        const float4* c0p = (const float4*)(Cs + (rg * 4 + 0) * 192);
        const float4* c1p = (const float4*)(Cs + (rg * 4 + 1) * 192);
        const float4* c2p = (const float4*)(Cs + (rg * 4 + 2) * 192);
        const float4* c3p = (const float4*)(Cs + (rg * 4 + 3) * 192);

        #pragma unroll 4
        for (int k4 = 0; k4 < 48; k4++) {
            float w0 = W1s[(k4 * 4 + 0) * 128 + j];
            float w1 = W1s[(k4 * 4 + 1) * 128 + j];
            float w2 = W1s[(k4 * 4 + 2) * 128 + j];
            float w3 = W1s[(k4 * 4 + 3) * 128 + j];
            float4 c0 = c0p[k4], c1 = c1p[k4], c2 = c2p[k4], c3 = c3p[k4];
            a0 = fmaf(c0.x, w0, a0); a0 = fmaf(c0.y, w1, a0);
            a0 = fmaf(c0.z, w2, a0); a0 = fmaf(c0.w, w3, a0);
            a1 = fmaf(c1.x, w0, a1); a1 = fmaf(c1.y, w1, a1);
            a1 = fmaf(c1.z, w2, a1); a1 = fmaf(c1.w, w3, a1);
            a2 = fmaf(c2.x, w0, a2); a2 = fmaf(c2.y, w1, a2);
            a2 = fmaf(c2.z, w2, a2); a2 = fmaf(c2.w, w3, a2);
            a3 = fmaf(c3.x, w0, a3); a3 = fmaf(c3.y, w1, a3);
            a3 = fmaf(c3.z, w2, a3); a3 = fmaf(c3.w, w3, a3);
        }
        Z1s[(rg * 4 + 0) * 128 + j] = fmaxf(a0, 0.f);
        Z1s[(rg * 4 + 1) * 128 + j] = fmaxf(a1, 0.f);
        Z1s[(rg * 4 + 2) * 128 + j] = fmaxf(a2, 0.f);
        Z1s[(rg * 4 + 3) * 128 + j] = fmaxf(a3, 0.f);
    }
    __syncthreads();

    // ---- layer 2: thread = (j: 1 col of 64, rg: 2 rows of 32)
    {
        const int j  = tid & 63;
        const int rg = tid >> 6;      // 0..15 -> rows 2rg, 2rg+1
        float bias = B2s[j];
        float a0 = bias, a1 = bias;

        const float4* c0p = (const float4*)(Z1s + (rg * 2 + 0) * 128);
        const float4* c1p = (const float4*)(Z1s + (rg * 2 + 1) * 128);

        #pragma unroll 4
        for (int k4 = 0; k4 < 32; k4++) {
            float w0 = W2s[(k4 * 4 + 0) * 64 + j];
            float w1 = W2s[(k4 * 4 + 1) * 64 + j];
            float w2 = W2s[(k4 * 4 + 2) * 64 + j];
            float w3 = W2s[(k4 * 4 + 3) * 64 + j];
            float4 c0 = c0p[k4], c1 = c1p[k4];
            a0 = fmaf(c0.x, w0, a0); a0 = fmaf(c0.y, w1, a0);
            a0 = fmaf(c0.z, w2, a0); a0 = fmaf(c0.w, w3, a0);
            a1 = fmaf(c1.x, w0, a1); a1 = fmaf(c1.y, w1, a1);
            a1 = fmaf(c1.z, w2, a1); a1 = fmaf(c1.w, w3, a1);
        }
        Z2s[(rg * 2 + 0) * 64 + j] = fmaxf(a0, 0.f);
        Z2s[(rg * 2 + 1) * 64 + j] = fmaxf(a1, 0.f);
    }
    __syncthreads();

    // ---- layer 3: warp per row (32 warps, 28 used)
    {
        const int w    = tid >> 5;
        const int lane = tid & 31;
        if (w < K2_ROWS) {
            const float* zr = Z2s + w * 64;
            float a = fmaf(zr[lane], W3s[lane], zr[lane + 32] * W3s[lane + 32]);
            #pragma unroll
            for (int o = 16; o; o >>= 1) a += __shfl_xor_sync(0xffffffffu, a, o);
            if (lane == 0 && r0 + w < nb)
                out[r0 + w] = 1.f / (1.f + __expf(-(a + __ldg(fb3))));
        }
    }
}

extern "C" void kernel_launch(void* const* d_in, const int* in_sizes, int n_in,
                              void* d_out, int out_size)
{
    const int*   item_ids = (const int*)  d_in[0];
    const int*   history  = (const int*)  d_in[1];
    const int*   hist_len = (const int*)  d_in[2];
    const float* emb      = (const float*)d_in[3];
    const float* aW1      = (const float*)d_in[4];
    const float* ab1      = (const float*)d_in[5];
    const float* aW2      = (const float*)d_in[6];
    // d_in[7] = ab2 — dropped (softmax shift-invariant)
    const float* fW1      = (const float*)d_in[8];
    const float* fb1      = (const float*)d_in[9];
    const float* fW2      = (const float*)d_in[10];
    const float* fb2      = (const float*)d_in[11];
    const float* fW3      = (const float*)d_in[12];
    const float* fb3      = (const float*)d_in[13];
    float* out = (float*)d_out;

    const int nb = in_sizes[0];

    cudaFuncSetAttribute(din_kernel, cudaFuncAttributeMaxDynamicSharedMemorySize, SMEM_BYTES);
    din_kernel<<<nb, NTHREADS, SMEM_BYTES>>>(
        item_ids, history, hist_len, emb, aW1, ab1, aW2);

    cudaFuncSetAttribute(mlp_kernel, cudaFuncAttributeMaxDynamicSharedMemorySize, K2_SMEM_BYTES);
    mlp_kernel<<<(nb + K2_ROWS - 1) / K2_ROWS, K2_THREADS, K2_SMEM_BYTES>>>(
        fW1, fb1, fW2, fb2, fW3, fb3, out, nb);
}

// round 14
// speedup vs baseline: 1.0257x; 1.0257x over previous
#include <cuda_runtime.h>
#include <cuda_bf16.h>
#include <math.h>

#define NTHREADS 256
#define HLEN     200
#define DIM      64
#define MAXB     4096

// ---- K1 dynamic smem layout ----
// bf16 tiles: 128B rows, chunk-XOR swizzle: byte(row,chunk)=row*128+((chunk^(row&7))<<4)
#define AHI_OFF   0                      // hist hi: 208 x 64 bf16 = 26624 B
#define BHI_OFF   26624                  // M hi: 64(k-rows) x 64 bf16 = 8192 B
#define F_TGT   8704                     // float index; 64
#define F_C     (F_TGT + 64)             // 64
#define F_W2    (F_C + 64)               // 64
#define F_SC    (F_W2 + 64)              // 200
#define F_RED   (F_SC + 200)             // 512
#define F_HID   (F_RED + 512)            // 200 (int)
#define F_SPAD  (F_HID + 200)            // 1
#define SMEM_FLOATS (F_SPAD + 4)
#define SMEM_BYTES  (SMEM_FLOATS * 4)    // ~39.3 KB -> 5 CTAs/SM

// inter-kernel scratch: comb = [tgt, pooled, pooled - tgt] per batch row
__device__ float g_comb[MAXB * 192];

__device__ __forceinline__ unsigned smem_u32(const void* p) {
    unsigned a;
    asm("{ .reg .u64 t; cvta.to.shared.u64 t, %1; cvt.u32.u64 %0, t; }"
        : "=r"(a) : "l"(p));
    return a;
}

#define LDSM_X4(r0, r1, r2, r3, addr) \
    asm volatile("ldmatrix.sync.aligned.m8n8.x4.shared.b16 {%0,%1,%2,%3}, [%4];" \
        : "=r"(r0), "=r"(r1), "=r"(r2), "=r"(r3) : "r"(addr))

#define LDSM_X2T(r0, r1, addr) \
    asm volatile("ldmatrix.sync.aligned.m8n8.x2.trans.shared.b16 {%0,%1}, [%2];" \
        : "=r"(r0), "=r"(r1) : "r"(addr))

#define MMA_BF16(d0, d1, d2, d3, a0, a1, a2, a3, b0, b1) \
    asm volatile("mma.sync.aligned.m16n8k16.row.col.f32.bf16.bf16.f32 " \
        "{%0,%1,%2,%3}, {%4,%5,%6,%7}, {%8,%9}, {%0,%1,%2,%3};" \
        : "+f"(d0), "+f"(d1), "+f"(d2), "+f"(d3) \
        : "r"(a0), "r"(a1), "r"(a2), "r"(a3), "r"(b0), "r"(b1))

__global__ __launch_bounds__(NTHREADS, 5)
void din_kernel(const int*   __restrict__ item_ids,
                const int*   __restrict__ history,
                const int*   __restrict__ hist_len,
                const float* __restrict__ emb,
                const float* __restrict__ aW1,
                const float* __restrict__ ab1,
                const float* __restrict__ aW2)
{
    extern __shared__ float sm[];
    char*  smc    = (char*)sm;
    float* tgt_s  = sm + F_TGT;
    float* c_s    = sm + F_C;
    float* w2_s   = sm + F_W2;
    float* sc_s   = sm + F_SC;
    float* red_s  = sm + F_RED;
    int*   hid_s  = (int*)(sm + F_HID);
    float* spad_s = sm + F_SPAD;

    const int b    = blockIdx.x;
    const int tid  = threadIdx.x;
    const int lane = tid & 31;
    const int wid  = tid >> 5;
    const unsigned sbase = smem_u32(sm);

    // ---- S0: history ids + target embedding + w2
    if (tid < HLEN) hid_s[tid] = history[b * HLEN + tid];
    if (tid < 16) {
        int iid = item_ids[b];
        ((float4*)tgt_s)[tid] = ((const float4*)(emb + (size_t)iid * DIM))[tid];
    }
    if (tid < DIM) w2_s[tid] = __ldg(aW2 + tid);
    __syncthreads();                                    // sync A

    const int hlen = hist_len[b];
    const int nt   = min(13, (hlen + 15) >> 4);   // live m16-tiles
    const int gtot = nt * 256;                    // rows*16 float4 chunks

    // ---- S1a: coalesced gather -> single bf16 hi tile (live rows only).
    for (int base = 0; base < gtot; base += 4 * NTHREADS) {
        float4 v[4];
        #pragma unroll
        for (int u = 0; u < 4; u++) {
            int idx = base + u * NTHREADS + tid;
            if (idx < gtot) {
                int row = idx >> 4;
                int c   = idx & 15;
                v[u] = make_float4(0.f, 0.f, 0.f, 0.f);
                if (row < hlen)
                    v[u] = ((const float4*)(emb + (size_t)hid_s[row] * DIM))[c];
            }
        }
        #pragma unroll
        for (int u = 0; u < 4; u++) {
            int idx = base + u * NTHREADS + tid;
            if (idx < gtot) {
                int row = idx >> 4;
                int c   = idx & 15;
                __nv_bfloat162 h01 = __floats2bfloat162_rn(v[u].x, v[u].y);
                __nv_bfloat162 h23 = __floats2bfloat162_rn(v[u].z, v[u].w);
                int byteoff = row * 128 + (((c >> 1) ^ (row & 7)) << 4) + (c & 1) * 8;
                *(uint2*)(smc + AHI_OFF + byteoff) =
                    make_uint2(*(unsigned*)&h01, *(unsigned*)&h23);
            }
        }
    }

    // ---- S1b: B tile (M[d][j] = A1[d][j] + tgt[d]*A3[d][j]) bf16, coalesced,
    //           fused with c_j partials (sum_d tgt[d]*A2[d][j]).
    {
        const int jp = tid & 31;
        const int g8 = tid >> 5;
        const int j0 = jp * 2;
        float p0 = 0.f, p1 = 0.f;
        #pragma unroll
        for (int d = g8 * 8; d < g8 * 8 + 8; d++) {
            float t = tgt_s[d];
            float2 a1 = __ldg((const float2*)(aW1 + d * DIM + j0));
            float2 a2 = __ldg((const float2*)(aW1 + (64 + d) * DIM + j0));
            float2 a3 = __ldg((const float2*)(aW1 + (128 + d) * DIM + j0));
            float m0 = fmaf(t, a3.x, a1.x);
            float m1 = fmaf(t, a3.y, a1.y);
            p0 = fmaf(t, a2.x, p0);
            p1 = fmaf(t, a2.y, p1);
            __nv_bfloat162 h = __floats2bfloat162_rn(m0, m1);
            int byteoff = d * 128 + ((((unsigned)j0 >> 3) ^ (d & 7)) << 4) + (j0 & 7) * 2;
            *(unsigned*)(smc + BHI_OFF + byteoff) = *(unsigned*)&h;
        }
        red_s[g8 * 64 + j0]     = p0;
        red_s[g8 * 64 + j0 + 1] = p1;
    }
    __syncthreads();                                    // sync B

    // ---- S2: finalize c_j; stage relu(c)*w2 for s_pad in red_s[256..319]
    if (tid < DIM) {
        float c = __ldg(ab1 + tid);
        #pragma unroll
        for (int g = 0; g < 8; g++) c += red_s[g * 64 + tid];
        c_s[tid]         = c;
        red_s[256 + tid] = fmaxf(c, 0.f) * w2_s[tid];
    }
    __syncthreads();                                    // sync C

    // ---- S3a: warp 0 reduces s_pad
    if (wid == 0) {
        float v = red_s[256 + lane] + red_s[288 + lane];
        #pragma unroll
        for (int o = 16; o; o >>= 1) v += __shfl_xor_sync(0xffffffffu, v, o);
        if (lane == 0) spad_s[0] = v;
    }

    // ---- S3b: scores GEMM on tensor pipe (single bf16 term).
    {
        const int m_off = ((lane >> 3) & 1) * 8 + (lane & 7);
        const int khalf = lane >> 4;
        const int bko   = ((lane >> 3) & 1) * 8 + (lane & 7);

        for (int mt = wid; mt < nt; mt += 8) {
            unsigned aH[4][4];
            const int r = mt * 16 + m_off;
            #pragma unroll
            for (int k = 0; k < 4; k++) {
                unsigned ad = sbase + AHI_OFF + r * 128 + ((((k << 1) + khalf) ^ (r & 7)) << 4);
                LDSM_X4(aH[k][0], aH[k][1], aH[k][2], aH[k][3], ad);
            }

            float s0 = 0.f, s1 = 0.f;
            #pragma unroll
            for (int n = 0; n < 8; n++) {
                float d0 = 0.f, d1 = 0.f, d2 = 0.f, d3 = 0.f;
                #pragma unroll
                for (int k = 0; k < 4; k++) {
                    int drow = k * 16 + bko;
                    unsigned bd = sbase + BHI_OFF + drow * 128 + ((n ^ (drow & 7)) << 4);
                    unsigned bh0, bh1;
                    LDSM_X2T(bh0, bh1, bd);
                    MMA_BF16(d0, d1, d2, d3, aH[k][0], aH[k][1], aH[k][2], aH[k][3], bh0, bh1);
                }
                int j0 = n * 8 + 2 * (lane & 3);
                float c0 = c_s[j0], c1 = c_s[j0 + 1];
                float w0 = w2_s[j0], w1 = w2_s[j0 + 1];
                s0 = fmaf(fmaxf(d0 + c0, 0.f), w0, s0);
                s0 = fmaf(fmaxf(d1 + c1, 0.f), w1, s0);
                s1 = fmaf(fmaxf(d2 + c0, 0.f), w0, s1);
                s1 = fmaf(fmaxf(d3 + c1, 0.f), w1, s1);
            }
            s0 += __shfl_xor_sync(0xffffffffu, s0, 1);
            s0 += __shfl_xor_sync(0xffffffffu, s0, 2);
            s1 += __shfl_xor_sync(0xffffffffu, s1, 1);
            s1 += __shfl_xor_sync(0xffffffffu, s1, 2);
            if ((lane & 3) == 0) {
                int l = mt * 16 + (lane >> 2);
                if (l < HLEN)     sc_s[l]     = s0;
                if (l + 8 < HLEN) sc_s[l + 8] = s1;
            }
        }
    }
    __syncthreads();                                    // sync D

    // ---- S4: fill rows beyond live tiles with s_pad
    {
        float sp = spad_s[0];
        int filled = nt * 16;
        for (int l = filled + tid; l < HLEN; l += NTHREADS) sc_s[l] = sp;
    }
    __syncthreads();                                    // sync E

    // ---- S5: softmax over sc_s[0..199]
    {
        float v = (tid < HLEN) ? sc_s[tid] : -INFINITY;
        float m = v;
        #pragma unroll
        for (int o = 16; o; o >>= 1) m = fmaxf(m, __shfl_xor_sync(0xffffffffu, m, o));
        if (lane == 0) red_s[wid] = m;
        __syncthreads();
        float mm = red_s[0];
        #pragma unroll
        for (int w = 1; w < 8; w++) mm = fmaxf(mm, red_s[w]);

        float e = (tid < HLEN) ? __expf(v - mm) : 0.f;
        float ssum = e;
        #pragma unroll
        for (int o = 16; o; o >>= 1) ssum += __shfl_xor_sync(0xffffffffu, ssum, o);
        if (lane == 0) red_s[8 + wid] = ssum;
        __syncthreads();
        float tot = red_s[8];
        #pragma unroll
        for (int w = 1; w < 8; w++) tot += red_s[8 + w];
        float inv = 1.f / tot;
        if (tid < HLEN) sc_s[tid] = e * inv;
    }
    __syncthreads();

    // ---- S6: pooled[d] = sum_{l<hlen} w[l]*emb[hid[l]][d] — exact fp32 from L2.
    {
        float p0 = 0.f, p1 = 0.f;
        const int dp = lane;
        for (int l = wid; l < hlen; l += 8) {
            float w = sc_s[l];
            float2 hv = __ldg((const float2*)(emb + (size_t)hid_s[l] * DIM) + dp);
            p0 = fmaf(w, hv.x, p0);
            p1 = fmaf(w, hv.y, p1);
        }
        red_s[wid * 64 + 2 * dp]     = p0;
        red_s[wid * 64 + 2 * dp + 1] = p1;
    }
    __syncthreads();

    // ---- S7: write comb = [tgt, pooled, pooled - tgt] to global scratch
    if (tid < DIM) {
        float pooled = 0.f;
        #pragma unroll
        for (int w = 0; w < 8; w++) pooled += red_s[w * 64 + tid];
        float tg = tgt_s[tid];
        float* gc = g_comb + (size_t)b * 192;
        gc[tid]        = tg;
        gc[64 + tid]   = pooled;
        gc[128 + tid]  = pooled - tg;
    }
}

// ============================ kernel 2: batched MLP ==========================
// R12 version (measured 21.6us): 256 threads, all weights in smem, 1 CTA/SM.
#define K2_ROWS 28

#define S2_W1   0                        // 192x128 = 24576
#define S2_W2   24576                    // 128x64  = 8192
#define S2_W3   32768                    // 64
#define S2_B1   32832                    // 128
#define S2_B2   32960                    // 64
#define S2_CMB  33024                    // 32x192  = 6144 (rows padded to 32)
#define S2_Z1   39168                    // 32x128  = 4096
#define S2_Z2   43264                    // 32x64   = 2048
#define K2_SMEM_FLOATS 45312
#define K2_SMEM_BYTES  (K2_SMEM_FLOATS * 4)

__global__ __launch_bounds__(256, 1)
void mlp_kernel(const float* __restrict__ fW1, const float* __restrict__ fb1,
                const float* __restrict__ fW2, const float* __restrict__ fb2,
                const float* __restrict__ fW3, const float* __restrict__ fb3,
                float* __restrict__ out, int nb)
{
    extern __shared__ float s2[];
    float* W1s = s2 + S2_W1;
    float* W2s = s2 + S2_W2;
    float* W3s = s2 + S2_W3;
    float* B1s = s2 + S2_B1;
    float* B2s = s2 + S2_B2;
    float* Cs  = s2 + S2_CMB;
    float* Z1s = s2 + S2_Z1;
    float* Z2s = s2 + S2_Z2;

    const int tid = threadIdx.x;
    const int r0  = blockIdx.x * K2_ROWS;

    for (int i = tid; i < 6144; i += 256) ((float4*)W1s)[i] = __ldg((const float4*)fW1 + i);
    for (int i = tid; i < 2048; i += 256) ((float4*)W2s)[i] = __ldg((const float4*)fW2 + i);
    if (tid < 64)  W3s[tid] = __ldg(fW3 + tid);
    if (tid < 128) B1s[tid] = __ldg(fb1 + tid);
    if (tid < 64)  B2s[tid] = __ldg(fb2 + tid);
    for (int i = tid; i < 32 * 48; i += 256) {
        int row = i / 48;
        int cc  = i - row * 48;
        float4 v = make_float4(0.f, 0.f, 0.f, 0.f);
        if (row < K2_ROWS && r0 + row < nb)
            v = ((const float4*)g_comb)[(size_t)(r0 + row) * 48 + cc];
        ((float4*)Cs)[i] = v;
    }
    __syncthreads();

    {
        const int j  = tid & 31;
        const int rg = tid >> 5;
        float4 acc0, acc1, acc2, acc3;
        float4 bias = ((const float4*)B1s)[j];
        acc0 = bias; acc1 = bias; acc2 = bias; acc3 = bias;

        const float4* c0p = (const float4*)(Cs + (rg * 4 + 0) * 192);
        const float4* c1p = (const float4*)(Cs + (rg * 4 + 1) * 192);
        const float4* c2p = (const float4*)(Cs + (rg * 4 + 2) * 192);
        const float4* c3p = (const float4*)(Cs + (rg * 4 + 3) * 192);
        const float4* wp  = (const float4*)W1s;

        #pragma unroll 4
        for (int k4 = 0; k4 < 48; k4++) {
            float4 w0 = wp[(k4 * 4 + 0) * 32 + j];
            float4 w1 = wp[(k4 * 4 + 1) * 32 + j];
            float4 w2 = wp[(k4 * 4 + 2) * 32 + j];
            float4 w3 = wp[(k4 * 4 + 3) * 32 + j];
            float4 c0 = c0p[k4], c1 = c1p[k4], c2 = c2p[k4], c3 = c3p[k4];
            #define L1STEP(acc, c) \
                acc.x = fmaf(c.x, w0.x, acc.x); acc.y = fmaf(c.x, w0.y, acc.y); \
                acc.z = fmaf(c.x, w0.z, acc.z); acc.w = fmaf(c.x, w0.w, acc.w); \
                acc.x = fmaf(c.y, w1.x, acc.x); acc.y = fmaf(c.y, w1.y, acc.y); \
                acc.z = fmaf(c.y, w1.z, acc.z); acc.w = fmaf(c.y, w1.w, acc.w); \
                acc.x = fmaf(c.z, w2.x, acc.x); acc.y = fmaf(c.z, w2.y, acc.y); \
                acc.z = fmaf(c.z, w2.z, acc.z); acc.w = fmaf(c.z, w2.w, acc.w); \
                acc.x = fmaf(c.w, w3.x, acc.x); acc.y = fmaf(c.w, w3.y, acc.y); \
                acc.z = fmaf(c.w, w3.z, acc.z); acc.w = fmaf(c.w, w3.w, acc.w);
            L1STEP(acc0, c0)
            L1STEP(acc1, c1)
            L1STEP(acc2, c2)
            L1STEP(acc3, c3)
            #undef L1STEP
        }
        #define RELU4(a) make_float4(fmaxf(a.x,0.f), fmaxf(a.y,0.f), fmaxf(a.z,0.f), fmaxf(a.w,0.f))
        ((float4*)(Z1s + (rg * 4 + 0) * 128))[j] = RELU4(acc0);
        ((float4*)(Z1s + (rg * 4 + 1) * 128))[j] = RELU4(acc1);
        ((float4*)(Z1s + (rg * 4 + 2) * 128))[j] = RELU4(acc2);
        ((float4*)(Z1s + (rg * 4 + 3) * 128))[j] = RELU4(acc3);
    }
    __syncthreads();

    {
        const int j  = tid & 15;
        const int rg = tid >> 4;
        float4 acc0, acc1;
        float4 bias = ((const float4*)B2s)[j];
        acc0 = bias; acc1 = bias;

        const float4* c0p = (const float4*)(Z1s + (rg * 2 + 0) * 128);
        const float4* c1p = (const float4*)(Z1s + (rg * 2 + 1) * 128);
        const float4* wp  = (const float4*)W2s;

        #pragma unroll 4
        for (int k4 = 0; k4 < 32; k4++) {
            float4 w0 = wp[(k4 * 4 + 0) * 16 + j];
            float4 w1 = wp[(k4 * 4 + 1) * 16 + j];
            float4 w2 = wp[(k4 * 4 + 2) * 16 + j];
            float4 w3 = wp[(k4 * 4 + 3) * 16 + j];
            float4 c0 = c0p[k4], c1 = c1p[k4];
            #define L2STEP(acc, c) \
                acc.x = fmaf(c.x, w0.x, acc.x); acc.y = fmaf(c.x, w0.y, acc.y); \
                acc.z = fmaf(c.x, w0.z, acc.z); acc.w = fmaf(c.x, w0.w, acc.w); \
                acc.x = fmaf(c.y, w1.x, acc.x); acc.y = fmaf(c.y, w1.y, acc.y); \
                acc.z = fmaf(c.y, w1.z, acc.z); acc.w = fmaf(c.y, w1.w, acc.w); \
                acc.x = fmaf(c.z, w2.x, acc.x); acc.y = fmaf(c.z, w2.y, acc.y); \
                acc.z = fmaf(c.z, w2.z, acc.z); acc.w = fmaf(c.z, w2.w, acc.w); \
                acc.x = fmaf(c.w, w3.x, acc.x); acc.y = fmaf(c.w, w3.y, acc.y); \
                acc.z = fmaf(c.w, w3.z, acc.z); acc.w = fmaf(c.w, w3.w, acc.w);
            L2STEP(acc0, c0)
            L2STEP(acc1, c1)
            #undef L2STEP
        }
        ((float4*)(Z2s + (rg * 2 + 0) * 64))[j] = RELU4(acc0);
        ((float4*)(Z2s + (rg * 2 + 1) * 64))[j] = RELU4(acc1);
        #undef RELU4
    }
    __syncthreads();

    {
        const int w    = tid >> 5;
        const int lane = tid & 31;
        float w3a = W3s[lane], w3b = W3s[lane + 32];
        float fb3v = __ldg(fb3);
        #pragma unroll
        for (int rr = 0; rr < 4; rr++) {
            int r = w * 4 + rr;
            const float* zr = Z2s + r * 64;
            float a = fmaf(zr[lane], w3a, zr[lane + 32] * w3b);
            #pragma unroll
            for (int o = 16; o; o >>= 1) a += __shfl_xor_sync(0xffffffffu, a, o);
            if (lane == 0 && r < K2_ROWS && r0 + r < nb)
                out[r0 + r] = 1.f / (1.f + __expf(-(a + fb3v)));
        }
    }
}

extern "C" void kernel_launch(void* const* d_in, const int* in_sizes, int n_in,
                              void* d_out, int out_size)
{
    const int*   item_ids = (const int*)  d_in[0];
    const int*   history  = (const int*)  d_in[1];
    const int*   hist_len = (const int*)  d_in[2];
    const float* emb      = (const float*)d_in[3];
    const float* aW1      = (const float*)d_in[4];
    const float* ab1      = (const float*)d_in[5];
    const float* aW2      = (const float*)d_in[6];
    // d_in[7] = ab2 — dropped (softmax shift-invariant)
    const float* fW1      = (const float*)d_in[8];
    const float* fb1      = (const float*)d_in[9];
    const float* fW2      = (const float*)d_in[10];
    const float* fb2      = (const float*)d_in[11];
    const float* fW3      = (const float*)d_in[12];
    const float* fb3      = (const float*)d_in[13];
    float* out = (float*)d_out;

    const int nb = in_sizes[0];

    cudaFuncSetAttribute(din_kernel, cudaFuncAttributeMaxDynamicSharedMemorySize, SMEM_BYTES);
    din_kernel<<<nb, NTHREADS, SMEM_BYTES>>>(
        item_ids, history, hist_len, emb, aW1, ab1, aW2);

    cudaFuncSetAttribute(mlp_kernel, cudaFuncAttributeMaxDynamicSharedMemorySize, K2_SMEM_BYTES);
    mlp_kernel<<<(nb + K2_ROWS - 1) / K2_ROWS, 256, K2_SMEM_BYTES>>>(
        fW1, fb1, fW2, fb2, fW3, fb3, out, nb);
}

// round 15
// speedup vs baseline: 1.0453x; 1.0191x over previous
#include <cuda_runtime.h>
#include <cuda_bf16.h>
#include <math.h>

#define NTHREADS 256
#define HLEN     200
#define DIM      64
#define MAXB     4096

// ---- K1 dynamic smem layout ----
// bf16 tiles: 128B rows, chunk-XOR swizzle: byte(row,chunk)=row*128+((chunk^(row&7))<<4)
#define AHI_OFF   0                      // hist hi: 208 x 64 bf16 = 26624 B
#define BHI_OFF   26624                  // M hi: 64(k-rows) x 64 bf16 = 8192 B
#define F_TGT   8704                     // float index; 64
#define F_C     (F_TGT + 64)             // 64
#define F_W2    (F_C + 64)               // 64
#define F_SC    (F_W2 + 64)              // 200
#define F_RED   (F_SC + 200)             // 512
#define F_HID   (F_RED + 512)            // 200 (int)
#define F_SPAD  (F_HID + 200)            // 1
#define SMEM_FLOATS (F_SPAD + 4)
#define SMEM_BYTES  (SMEM_FLOATS * 4)    // ~39.3 KB -> 4 CTAs/SM

// inter-kernel scratch
__device__ float g_comb[MAXB * 192];
// pre-packed attention weights (written by pack_kernel each call):
//   g_A13[(d*64+j)*2 + {0,1}] = bf16(A1[d][j]), bf16(A3[d][j])
//   g_A2[d*64+j]              = bf16(A2[d][j])
__device__ __align__(16) __nv_bfloat16 g_A13[DIM * DIM * 2];
__device__ __align__(16) __nv_bfloat16 g_A2[DIM * DIM];

__device__ __forceinline__ unsigned smem_u32(const void* p) {
    unsigned a;
    asm("{ .reg .u64 t; cvta.to.shared.u64 t, %1; cvt.u32.u64 %0, t; }"
        : "=r"(a) : "l"(p));
    return a;
}

#define LDSM_X4(r0, r1, r2, r3, addr) \
    asm volatile("ldmatrix.sync.aligned.m8n8.x4.shared.b16 {%0,%1,%2,%3}, [%4];" \
        : "=r"(r0), "=r"(r1), "=r"(r2), "=r"(r3) : "r"(addr))

#define LDSM_X2T(r0, r1, addr) \
    asm volatile("ldmatrix.sync.aligned.m8n8.x2.trans.shared.b16 {%0,%1}, [%2];" \
        : "=r"(r0), "=r"(r1) : "r"(addr))

#define MMA_BF16(d0, d1, d2, d3, a0, a1, a2, a3, b0, b1) \
    asm volatile("mma.sync.aligned.m16n8k16.row.col.f32.bf16.bf16.f32 " \
        "{%0,%1,%2,%3}, {%4,%5,%6,%7}, {%8,%9}, {%0,%1,%2,%3};" \
        : "+f"(d0), "+f"(d1), "+f"(d2), "+f"(d3) \
        : "r"(a0), "r"(a1), "r"(a2), "r"(a3), "r"(b0), "r"(b1))

// ==================== kernel 0: pack aW1 -> bf16 arrays ======================
__global__ __launch_bounds__(256)
void pack_kernel(const float* __restrict__ aW1)
{
    int idx = blockIdx.x * 256 + threadIdx.x;   // 0..4095
    int d = idx >> 6, j = idx & 63;
    float a1 = __ldg(aW1 + d * DIM + j);
    float a2 = __ldg(aW1 + (64 + d) * DIM + j);
    float a3 = __ldg(aW1 + (128 + d) * DIM + j);
    g_A13[idx * 2]     = __float2bfloat16(a1);
    g_A13[idx * 2 + 1] = __float2bfloat16(a3);
    g_A2[idx]          = __float2bfloat16(a2);
}

__global__ __launch_bounds__(NTHREADS, 4)
void din_kernel(const int*   __restrict__ item_ids,
                const int*   __restrict__ history,
                const int*   __restrict__ hist_len,
                const float* __restrict__ emb,
                const float* __restrict__ ab1,
                const float* __restrict__ aW2)
{
    extern __shared__ float sm[];
    char*  smc    = (char*)sm;
    float* tgt_s  = sm + F_TGT;
    float* c_s    = sm + F_C;
    float* w2_s   = sm + F_W2;
    float* sc_s   = sm + F_SC;
    float* red_s  = sm + F_RED;
    int*   hid_s  = (int*)(sm + F_HID);
    float* spad_s = sm + F_SPAD;

    const int b    = blockIdx.x;
    const int tid  = threadIdx.x;
    const int lane = tid & 31;
    const int wid  = tid >> 5;
    const unsigned sbase = smem_u32(sm);

    // ---- S0: history ids + target embedding + w2
    if (tid < HLEN) hid_s[tid] = history[b * HLEN + tid];
    if (tid < 16) {
        int iid = item_ids[b];
        ((float4*)tgt_s)[tid] = ((const float4*)(emb + (size_t)iid * DIM))[tid];
    }
    if (tid < DIM) w2_s[tid] = __ldg(aW2 + tid);
    __syncthreads();                                    // sync A

    const int hlen = hist_len[b];
    const int nt   = min(13, (hlen + 15) >> 4);   // live m16-tiles
    const int gtot = nt * 256;                    // rows*16 float4 chunks

    // ---- S1a: coalesced gather -> single bf16 hi tile (live rows only).
    for (int base = 0; base < gtot; base += 4 * NTHREADS) {
        float4 v[4];
        #pragma unroll
        for (int u = 0; u < 4; u++) {
            int idx = base + u * NTHREADS + tid;
            if (idx < gtot) {
                int row = idx >> 4;
                int c   = idx & 15;
                v[u] = make_float4(0.f, 0.f, 0.f, 0.f);
                if (row < hlen)
                    v[u] = ((const float4*)(emb + (size_t)hid_s[row] * DIM))[c];
            }
        }
        #pragma unroll
        for (int u = 0; u < 4; u++) {
            int idx = base + u * NTHREADS + tid;
            if (idx < gtot) {
                int row = idx >> 4;
                int c   = idx & 15;
                __nv_bfloat162 h01 = __floats2bfloat162_rn(v[u].x, v[u].y);
                __nv_bfloat162 h23 = __floats2bfloat162_rn(v[u].z, v[u].w);
                int byteoff = row * 128 + (((c >> 1) ^ (row & 7)) << 4) + (c & 1) * 8;
                *(uint2*)(smc + AHI_OFF + byteoff) =
                    make_uint2(*(unsigned*)&h01, *(unsigned*)&h23);
            }
        }
    }

    // ---- S1b: B tile from PACKED bf16 weights (24KB total vs 49KB fp32),
    //           fused with c_j partials. Fully coalesced uint2/bf162 loads.
    {
        const int jp = tid & 31;
        const int g8 = tid >> 5;
        const int j0 = jp * 2;
        float p0 = 0.f, p1 = 0.f;
        #pragma unroll
        for (int d = g8 * 8; d < g8 * 8 + 8; d++) {
            float t = tgt_s[d];
            uint2 raw = *(const uint2*)(g_A13 + (size_t)(d * 64 + j0) * 2);
            __nv_bfloat162 b0 = *(__nv_bfloat162*)&raw.x;   // (a1_j0, a3_j0)
            __nv_bfloat162 b1 = *(__nv_bfloat162*)&raw.y;   // (a1_j1, a3_j1)
            float m0 = fmaf(t, __bfloat162float(b0.y), __bfloat162float(b0.x));
            float m1 = fmaf(t, __bfloat162float(b1.y), __bfloat162float(b1.x));
            __nv_bfloat162 a2p = *(const __nv_bfloat162*)(g_A2 + d * 64 + j0);
            p0 = fmaf(t, __bfloat162float(a2p.x), p0);
            p1 = fmaf(t, __bfloat162float(a2p.y), p1);
            __nv_bfloat162 h = __floats2bfloat162_rn(m0, m1);
            int byteoff = d * 128 + ((((unsigned)j0 >> 3) ^ (d & 7)) << 4) + (j0 & 7) * 2;
            *(unsigned*)(smc + BHI_OFF + byteoff) = *(unsigned*)&h;
        }
        red_s[g8 * 64 + j0]     = p0;
        red_s[g8 * 64 + j0 + 1] = p1;
    }
    __syncthreads();                                    // sync B

    // ---- S2: finalize c_j; stage relu(c)*w2 for s_pad in red_s[256..319]
    if (tid < DIM) {
        float c = __ldg(ab1 + tid);
        #pragma unroll
        for (int g = 0; g < 8; g++) c += red_s[g * 64 + tid];
        c_s[tid]         = c;
        red_s[256 + tid] = fmaxf(c, 0.f) * w2_s[tid];
    }
    __syncthreads();                                    // sync C

    // ---- S3a: warp 0 reduces s_pad
    if (wid == 0) {
        float v = red_s[256 + lane] + red_s[288 + lane];
        #pragma unroll
        for (int o = 16; o; o >>= 1) v += __shfl_xor_sync(0xffffffffu, v, o);
        if (lane == 0) spad_s[0] = v;
    }

    // ---- S3b: scores GEMM on tensor pipe (single bf16 term).
    {
        const int m_off = ((lane >> 3) & 1) * 8 + (lane & 7);
        const int khalf = lane >> 4;
        const int bko   = ((lane >> 3) & 1) * 8 + (lane & 7);

        for (int mt = wid; mt < nt; mt += 8) {
            unsigned aH[4][4];
            const int r = mt * 16 + m_off;
            #pragma unroll
            for (int k = 0; k < 4; k++) {
                unsigned ad = sbase + AHI_OFF + r * 128 + ((((k << 1) + khalf) ^ (r & 7)) << 4);
                LDSM_X4(aH[k][0], aH[k][1], aH[k][2], aH[k][3], ad);
            }

            float s0 = 0.f, s1 = 0.f;
            #pragma unroll
            for (int n = 0; n < 8; n++) {
                float d0 = 0.f, d1 = 0.f, d2 = 0.f, d3 = 0.f;
                #pragma unroll
                for (int k = 0; k < 4; k++) {
                    int drow = k * 16 + bko;
                    unsigned bd = sbase + BHI_OFF + drow * 128 + ((n ^ (drow & 7)) << 4);
                    unsigned bh0, bh1;
                    LDSM_X2T(bh0, bh1, bd);
                    MMA_BF16(d0, d1, d2, d3, aH[k][0], aH[k][1], aH[k][2], aH[k][3], bh0, bh1);
                }
                int j0 = n * 8 + 2 * (lane & 3);
                float c0 = c_s[j0], c1 = c_s[j0 + 1];
                float w0 = w2_s[j0], w1 = w2_s[j0 + 1];
                s0 = fmaf(fmaxf(d0 + c0, 0.f), w0, s0);
                s0 = fmaf(fmaxf(d1 + c1, 0.f), w1, s0);
                s1 = fmaf(fmaxf(d2 + c0, 0.f), w0, s1);
                s1 = fmaf(fmaxf(d3 + c1, 0.f), w1, s1);
            }
            s0 += __shfl_xor_sync(0xffffffffu, s0, 1);
            s0 += __shfl_xor_sync(0xffffffffu, s0, 2);
            s1 += __shfl_xor_sync(0xffffffffu, s1, 1);
            s1 += __shfl_xor_sync(0xffffffffu, s1, 2);
            if ((lane & 3) == 0) {
                int l = mt * 16 + (lane >> 2);
                if (l < HLEN)     sc_s[l]     = s0;
                if (l + 8 < HLEN) sc_s[l + 8] = s1;
            }
        }
    }
    __syncthreads();                                    // sync D

    // ---- S4: fill rows beyond live tiles with s_pad
    {
        float sp = spad_s[0];
        int filled = nt * 16;
        for (int l = filled + tid; l < HLEN; l += NTHREADS) sc_s[l] = sp;
    }
    __syncthreads();                                    // sync E

    // ---- S5: softmax over sc_s[0..199]
    {
        float v = (tid < HLEN) ? sc_s[tid] : -INFINITY;
        float m = v;
        #pragma unroll
        for (int o = 16; o; o >>= 1) m = fmaxf(m, __shfl_xor_sync(0xffffffffu, m, o));
        if (lane == 0) red_s[wid] = m;
        __syncthreads();
        float mm = red_s[0];
        #pragma unroll
        for (int w = 1; w < 8; w++) mm = fmaxf(mm, red_s[w]);

        float e = (tid < HLEN) ? __expf(v - mm) : 0.f;
        float ssum = e;
        #pragma unroll
        for (int o = 16; o; o >>= 1) ssum += __shfl_xor_sync(0xffffffffu, ssum, o);
        if (lane == 0) red_s[8 + wid] = ssum;
        __syncthreads();
        float tot = red_s[8];
        #pragma unroll
        for (int w = 1; w < 8; w++) tot += red_s[8 + w];
        float inv = 1.f / tot;
        if (tid < HLEN) sc_s[tid] = e * inv;
    }
    __syncthreads();

    // ---- S6: pooled[d] = sum_{l<hlen} w[l]*emb[hid[l]][d] — exact fp32 from L2.
    {
        float p0 = 0.f, p1 = 0.f;
        const int dp = lane;
        for (int l = wid; l < hlen; l += 8) {
            float w = sc_s[l];
            float2 hv = __ldg((const float2*)(emb + (size_t)hid_s[l] * DIM) + dp);
            p0 = fmaf(w, hv.x, p0);
            p1 = fmaf(w, hv.y, p1);
        }
        red_s[wid * 64 + 2 * dp]     = p0;
        red_s[wid * 64 + 2 * dp + 1] = p1;
    }
    __syncthreads();

    // ---- S7: write comb = [tgt, pooled, pooled - tgt] to global scratch
    if (tid < DIM) {
        float pooled = 0.f;
        #pragma unroll
        for (int w = 0; w < 8; w++) pooled += red_s[w * 64 + tid];
        float tg = tgt_s[tid];
        float* gc = g_comb + (size_t)b * 192;
        gc[tid]        = tg;
        gc[64 + tid]   = pooled;
        gc[128 + tid]  = pooled - tg;
    }
}

// ============================ kernel 2: batched MLP ==========================
// R12 version (measured 21.6us): 256 threads, all weights in smem, 1 CTA/SM.
#define K2_ROWS 28

#define S2_W1   0                        // 192x128 = 24576
#define S2_W2   24576                    // 128x64  = 8192
#define S2_W3   32768                    // 64
#define S2_B1   32832                    // 128
#define S2_B2   32960                    // 64
#define S2_CMB  33024                    // 32x192  = 6144 (rows padded to 32)
#define S2_Z1   39168                    // 32x128  = 4096
#define S2_Z2   43264                    // 32x64   = 2048
#define K2_SMEM_FLOATS 45312
#define K2_SMEM_BYTES  (K2_SMEM_FLOATS * 4)

__global__ __launch_bounds__(256, 1)
void mlp_kernel(const float* __restrict__ fW1, const float* __restrict__ fb1,
                const float* __restrict__ fW2, const float* __restrict__ fb2,
                const float* __restrict__ fW3, const float* __restrict__ fb3,
                float* __restrict__ out, int nb)
{
    extern __shared__ float s2[];
    float* W1s = s2 + S2_W1;
    float* W2s = s2 + S2_W2;
    float* W3s = s2 + S2_W3;
    float* B1s = s2 + S2_B1;
    float* B2s = s2 + S2_B2;
    float* Cs  = s2 + S2_CMB;
    float* Z1s = s2 + S2_Z1;
    float* Z2s = s2 + S2_Z2;

    const int tid = threadIdx.x;
    const int r0  = blockIdx.x * K2_ROWS;

    for (int i = tid; i < 6144; i += 256) ((float4*)W1s)[i] = __ldg((const float4*)fW1 + i);
    for (int i = tid; i < 2048; i += 256) ((float4*)W2s)[i] = __ldg((const float4*)fW2 + i);
    if (tid < 64)  W3s[tid] = __ldg(fW3 + tid);
    if (tid < 128) B1s[tid] = __ldg(fb1 + tid);
    if (tid < 64)  B2s[tid] = __ldg(fb2 + tid);
    for (int i = tid; i < 32 * 48; i += 256) {
        int row = i / 48;
        int cc  = i - row * 48;
        float4 v = make_float4(0.f, 0.f, 0.f, 0.f);
        if (row < K2_ROWS && r0 + row < nb)
            v = ((const float4*)g_comb)[(size_t)(r0 + row) * 48 + cc];
        ((float4*)Cs)[i] = v;
    }
    __syncthreads();

    {
        const int j  = tid & 31;
        const int rg = tid >> 5;
        float4 acc0, acc1, acc2, acc3;
        float4 bias = ((const float4*)B1s)[j];
        acc0 = bias; acc1 = bias; acc2 = bias; acc3 = bias;

        const float4* c0p = (const float4*)(Cs + (rg * 4 + 0) * 192);
        const float4* c1p = (const float4*)(Cs + (rg * 4 + 1) * 192);
        const float4* c2p = (const float4*)(Cs + (rg * 4 + 2) * 192);
        const float4* c3p = (const float4*)(Cs + (rg * 4 + 3) * 192);
        const float4* wp  = (const float4*)W1s;

        #pragma unroll 4
        for (int k4 = 0; k4 < 48; k4++) {
            float4 w0 = wp[(k4 * 4 + 0) * 32 + j];
            float4 w1 = wp[(k4 * 4 + 1) * 32 + j];
            float4 w2 = wp[(k4 * 4 + 2) * 32 + j];
            float4 w3 = wp[(k4 * 4 + 3) * 32 + j];
            float4 c0 = c0p[k4], c1 = c1p[k4], c2 = c2p[k4], c3 = c3p[k4];
            #define L1STEP(acc, c) \
                acc.x = fmaf(c.x, w0.x, acc.x); acc.y = fmaf(c.x, w0.y, acc.y); \
                acc.z = fmaf(c.x, w0.z, acc.z); acc.w = fmaf(c.x, w0.w, acc.w); \
                acc.x = fmaf(c.y, w1.x, acc.x); acc.y = fmaf(c.y, w1.y, acc.y); \
                acc.z = fmaf(c.y, w1.z, acc.z); acc.w = fmaf(c.y, w1.w, acc.w); \
                acc.x = fmaf(c.z, w2.x, acc.x); acc.y = fmaf(c.z, w2.y, acc.y); \
                acc.z = fmaf(c.z, w2.z, acc.z); acc.w = fmaf(c.z, w2.w, acc.w); \
                acc.x = fmaf(c.w, w3.x, acc.x); acc.y = fmaf(c.w, w3.y, acc.y); \
                acc.z = fmaf(c.w, w3.z, acc.z); acc.w = fmaf(c.w, w3.w, acc.w);
            L1STEP(acc0, c0)
            L1STEP(acc1, c1)
            L1STEP(acc2, c2)
            L1STEP(acc3, c3)
            #undef L1STEP
        }
        #define RELU4(a) make_float4(fmaxf(a.x,0.f), fmaxf(a.y,0.f), fmaxf(a.z,0.f), fmaxf(a.w,0.f))
        ((float4*)(Z1s + (rg * 4 + 0) * 128))[j] = RELU4(acc0);
        ((float4*)(Z1s + (rg * 4 + 1) * 128))[j] = RELU4(acc1);
        ((float4*)(Z1s + (rg * 4 + 2) * 128))[j] = RELU4(acc2);
        ((float4*)(Z1s + (rg * 4 + 3) * 128))[j] = RELU4(acc3);
    }
    __syncthreads();

    {
        const int j  = tid & 15;
        const int rg = tid >> 4;
        float4 acc0, acc1;
        float4 bias = ((const float4*)B2s)[j];
        acc0 = bias; acc1 = bias;

        const float4* c0p = (const float4*)(Z1s + (rg * 2 + 0) * 128);
        const float4* c1p = (const float4*)(Z1s + (rg * 2 + 1) * 128);
        const float4* wp  = (const float4*)W2s;

        #pragma unroll 4
        for (int k4 = 0; k4 < 32; k4++) {
            float4 w0 = wp[(k4 * 4 + 0) * 16 + j];
            float4 w1 = wp[(k4 * 4 + 1) * 16 + j];
            float4 w2 = wp[(k4 * 4 + 2) * 16 + j];
            float4 w3 = wp[(k4 * 4 + 3) * 16 + j];
            float4 c0 = c0p[k4], c1 = c1p[k4];
            #define L2STEP(acc, c) \
                acc.x = fmaf(c.x, w0.x, acc.x); acc.y = fmaf(c.x, w0.y, acc.y); \
                acc.z = fmaf(c.x, w0.z, acc.z); acc.w = fmaf(c.x, w0.w, acc.w); \
                acc.x = fmaf(c.y, w1.x, acc.x); acc.y = fmaf(c.y, w1.y, acc.y); \
                acc.z = fmaf(c.y, w1.z, acc.z); acc.w = fmaf(c.y, w1.w, acc.w); \
                acc.x = fmaf(c.z, w2.x, acc.x); acc.y = fmaf(c.z, w2.y, acc.y); \
                acc.z = fmaf(c.z, w2.z, acc.z); acc.w = fmaf(c.z, w2.w, acc.w); \
                acc.x = fmaf(c.w, w3.x, acc.x); acc.y = fmaf(c.w, w3.y, acc.y); \
                acc.z = fmaf(c.w, w3.z, acc.z); acc.w = fmaf(c.w, w3.w, acc.w);
            L2STEP(acc0, c0)
            L2STEP(acc1, c1)
            #undef L2STEP
        }
        ((float4*)(Z2s + (rg * 2 + 0) * 64))[j] = RELU4(acc0);
        ((float4*)(Z2s + (rg * 2 + 1) * 64))[j] = RELU4(acc1);
        #undef RELU4
    }
    __syncthreads();

    {
        const int w    = tid >> 5;
        const int lane = tid & 31;
        float w3a = W3s[lane], w3b = W3s[lane + 32];
        float fb3v = __ldg(fb3);
        #pragma unroll
        for (int rr = 0; rr < 4; rr++) {
            int r = w * 4 + rr;
            const float* zr = Z2s + r * 64;
            float a = fmaf(zr[lane], w3a, zr[lane + 32] * w3b);
            #pragma unroll
            for (int o = 16; o; o >>= 1) a += __shfl_xor_sync(0xffffffffu, a, o);
            if (lane == 0 && r < K2_ROWS && r0 + r < nb)
                out[r0 + r] = 1.f / (1.f + __expf(-(a + fb3v)));
        }
    }
}

extern "C" void kernel_launch(void* const* d_in, const int* in_sizes, int n_in,
                              void* d_out, int out_size)
{
    const int*   item_ids = (const int*)  d_in[0];
    const int*   history  = (const int*)  d_in[1];
    const int*   hist_len = (const int*)  d_in[2];
    const float* emb      = (const float*)d_in[3];
    const float* aW1      = (const float*)d_in[4];
    const float* ab1      = (const float*)d_in[5];
    const float* aW2      = (const float*)d_in[6];
    // d_in[7] = ab2 — dropped (softmax shift-invariant)
    const float* fW1      = (const float*)d_in[8];
    const float* fb1      = (const float*)d_in[9];
    const float* fW2      = (const float*)d_in[10];
    const float* fb2      = (const float*)d_in[11];
    const float* fW3      = (const float*)d_in[12];
    const float* fb3      = (const float*)d_in[13];
    float* out = (float*)d_out;

    const int nb = in_sizes[0];

    pack_kernel<<<16, 256>>>(aW1);

    cudaFuncSetAttribute(din_kernel, cudaFuncAttributeMaxDynamicSharedMemorySize, SMEM_BYTES);
    din_kernel<<<nb, NTHREADS, SMEM_BYTES>>>(
        item_ids, history, hist_len, emb, ab1, aW2);

    cudaFuncSetAttribute(mlp_kernel, cudaFuncAttributeMaxDynamicSharedMemorySize, K2_SMEM_BYTES);
    mlp_kernel<<<(nb + K2_ROWS - 1) / K2_ROWS, 256, K2_SMEM_BYTES>>>(
        fW1, fb1, fW2, fb2, fW3, fb3, out, nb);
}